// round 13
// baseline (speedup 1.0000x reference)
#include <cuda_runtime.h>
#include <cuda_bf16.h>
#include <cuda_fp16.h>
#include <mma.h>
#include <cstdint>

using namespace nvcuda;

#define NN 50000
#define NE 800000
#define NG 512
#define DD 64
#define DOUT 32
#define LN_EPS 1e-5f
#define MM_ROWS 128
#define NPB 16                  // nodes per block in fused gather+mm

// ---------------- scratch (static device globals; 16B aligned) --------------
__device__ int g_is64;                            // 1 if index inputs are int64
__device__ int g_alloc;                           // CSR allocation cursor
__device__ __align__(16) int    g_edeg[NN];       // edge in-degree (no self loop)
__device__ __align__(16) float  g_dinv[NN];
__device__ __align__(16) int    g_src[NE];
__device__ __align__(16) int    g_dst[NE];
__device__ __align__(16) int    g_rowstart[NN];   // CSR row offsets (unordered alloc)
__device__ __align__(16) int    g_cursor[NN];
__device__ __align__(16) int2   g_csr[NE];        // CSR: {src, weight bits}
__device__ __align__(16) __half g_hwA[NN * DD];   // h @ W ping
__device__ __align__(16) __half g_hwB[NN * DD];   // h @ W pong
__device__ __align__(16) float  g_pool[NG * DD];
__device__ __align__(16) float  g_cnt[NG];

// ---------------- helpers ---------------------------------------------------
__device__ __forceinline__ float warp_sum(float v) {
    #pragma unroll
    for (int o = 16; o > 0; o >>= 1) v += __shfl_xor_sync(0xffffffffu, v, o);
    return v;
}
__device__ __forceinline__ int clampi(int v, int hi) {   // [0, hi)
    return v < 0 ? 0 : (v >= hi ? hi - 1 : v);
}
__device__ __forceinline__ int read_idx(const void* p, int i) {
    if (g_is64) return (int)((const long long*)p)[i];
    return ((const int*)p)[i];
}

// gather + bias + LN + ReLU for one node; returns the lane's 2 columns.
__device__ __forceinline__ float2 gather_node(const __half2* hw2, int n, int lane,
                                              const float* b, const float* lw,
                                              const float* lb) {
    float ws = g_dinv[n]; ws *= ws;
    float2 bb = reinterpret_cast<const float2*>(b)[lane];
    float2 self = __half22float2(hw2[n * 32 + lane]);
    float a0 = bb.x + ws * self.x;
    float a1 = bb.y + ws * self.y;

    int beg = g_rowstart[n];
    int cnt = g_edeg[n];
    #pragma unroll 4
    for (int j = 0; j < cnt; j++) {
        int2 sw = g_csr[beg + j];
        float w = __int_as_float(sw.y);
        float2 v = __half22float2(hw2[sw.x * 32 + lane]);
        a0 += w * v.x;
        a1 += w * v.y;
    }

    float mu = warp_sum(a0 + a1) * (1.0f / DD);
    float d0 = a0 - mu, d1 = a1 - mu;
    float var = warp_sum(d0 * d0 + d1 * d1) * (1.0f / DD);
    float rs = rsqrtf(var + LN_EPS);
    float2 w2 = reinterpret_cast<const float2*>(lw)[lane];
    float2 lb2 = reinterpret_cast<const float2*>(lb)[lane];
    return make_float2(fmaxf(d0 * rs * w2.x + lb2.x, 0.0f),
                       fmaxf(d1 * rs * w2.y + lb2.y, 0.0f));
}

// ---------------- setup kernels ---------------------------------------------
__global__ void k_prep(const int* __restrict__ raw) {
    int i = blockIdx.x * blockDim.x + threadIdx.x;
    if (i < NN) g_edeg[i] = 0;
    if (i < NG) g_cnt[i] = 0.0f;
    if (i == 0) g_alloc = 0;
    if (blockIdx.x == 0) {
        __shared__ int any;
        if (threadIdx.x == 0) any = 0;
        __syncthreads();
        if (raw[2 * threadIdx.x + 1] != 0) atomicOr(&any, 1);
        __syncthreads();
        if (threadIdx.x == 0) g_is64 = (any == 0) ? 1 : 0;
    }
}

__global__ void k_deg(const void* __restrict__ ei) {
    int e = blockIdx.x * blockDim.x + threadIdx.x;
    if (e >= NE) return;
    int s = clampi(read_idx(ei, e), NN);
    int d = clampi(read_idx(ei, NE + e), NN);
    g_src[e] = s;
    g_dst[e] = d;
    atomicAdd(&g_edeg[d], 1);
}

// CSR slot allocation (order-free) + dinv + pool zero + graph-size histogram.
__global__ void k_alloc(const void* __restrict__ batch) {
    int i = blockIdx.x * blockDim.x + threadIdx.x;
    if (i < NG * DD) g_pool[i] = 0.0f;
    if (i >= NN) return;
    int d = g_edeg[i];
    g_dinv[i] = rsqrtf((float)(d + 1));   // +1 self loop
    int r = atomicAdd(&g_alloc, d);
    g_rowstart[i] = r;
    g_cursor[i] = r;
    atomicAdd(&g_cnt[clampi(read_idx(batch, i), NG)], 1.0f);
}

__global__ void k_bucket() {
    int e = blockIdx.x * blockDim.x + threadIdx.x;
    if (e >= NE) return;
    int s = g_src[e];
    int d = g_dst[e];
    float w = g_dinv[s] * g_dinv[d];
    int pos = atomicAdd(&g_cursor[d], 1);
    g_csr[pos] = make_int2(s, __float_as_int(w));
}

// ---------------- layer-0 GEMM: g_hwA = x @ W (wmma) -------------------------
__global__ void k_matmul0(const float* __restrict__ xin, const float* __restrict__ W) {
    __shared__ __align__(16) char sbuf[128 * 72 * 4];
    __half (*As)[72] = reinterpret_cast<__half (*)[72]>(sbuf);
    __half (*Bs)[72] = reinterpret_cast<__half (*)[72]>(sbuf + 128 * 72 * 2);
    float  (*Cs)[72] = reinterpret_cast<float  (*)[72]>(sbuf);

    int t = threadIdx.x;
    int base = blockIdx.x * MM_ROWS;
    int row = t >> 1;
    int part = (t & 1) * 32;
    int grow = base + row;

    if (grow < NN) {
        const float4* src = reinterpret_cast<const float4*>(&xin[grow * DD + part]);
        __half2* dst = reinterpret_cast<__half2*>(&As[row][part]);
        #pragma unroll
        for (int i = 0; i < 8; i++) {
            float4 v = src[i];
            dst[2 * i]     = __floats2half2_rn(v.x, v.y);
            dst[2 * i + 1] = __floats2half2_rn(v.z, v.w);
        }
    } else {
        int4 z = make_int4(0, 0, 0, 0);
        int4* dst = reinterpret_cast<int4*>(&As[row][part]);
        #pragma unroll
        for (int i = 0; i < 4; i++) dst[i] = z;
    }
    if (t < 128) {
        int brow = t >> 1;
        int bpart = (t & 1) * 32;
        const float4* src = reinterpret_cast<const float4*>(&W[brow * DD + bpart]);
        __half2* dst = reinterpret_cast<__half2*>(&Bs[brow][bpart]);
        #pragma unroll
        for (int i = 0; i < 8; i++) {
            float4 v = src[i];
            dst[2 * i]     = __floats2half2_rn(v.x, v.y);
            dst[2 * i + 1] = __floats2half2_rn(v.z, v.w);
        }
    }
    __syncthreads();

    int w = t >> 5;
    wmma::fragment<wmma::accumulator, 16, 16, 16, float> acc[4];
    #pragma unroll
    for (int n = 0; n < 4; n++) wmma::fill_fragment(acc[n], 0.0f);
    #pragma unroll
    for (int k = 0; k < 4; k++) {
        wmma::fragment<wmma::matrix_a, 16, 16, 16, __half, wmma::row_major> af;
        wmma::load_matrix_sync(af, &As[w * 16][k * 16], 72);
        #pragma unroll
        for (int n = 0; n < 4; n++) {
            wmma::fragment<wmma::matrix_b, 16, 16, 16, __half, wmma::row_major> bf;
            wmma::load_matrix_sync(bf, &Bs[k * 16][n * 16], 72);
            wmma::mma_sync(acc[n], af, bf, acc[n]);
        }
    }
    __syncthreads();
    #pragma unroll
    for (int n = 0; n < 4; n++)
        wmma::store_matrix_sync(&Cs[w * 16][n * 16], acc[n], 72, wmma::mem_row_major);
    __syncthreads();

    if (grow < NN) {
        __half2* dst = reinterpret_cast<__half2*>(&g_hwA[grow * DD + part]);
        #pragma unroll
        for (int i = 0; i < 16; i++)
            dst[i] = __floats2half2_rn(Cs[row][part + 2 * i], Cs[row][part + 2 * i + 1]);
    }
}

// ---------------- fused gather + LN + ReLU + next-layer GEMM ------------------
// 256 threads, 8 warps, 16 nodes/block (2 per warp). dir=0: A->B, dir=1: B->A.
__global__ void k_gather_mm(int dir,
                            const float* __restrict__ b,
                            const float* __restrict__ lw,
                            const float* __restrict__ lb,
                            const float* __restrict__ Wn) {
    __shared__ __align__(32) __half Ws[DD][72];     // next-layer weights
    __shared__ __align__(32) __half Hs[NPB][72];    // post-LN activations
    __shared__ __align__(32) float  Cs[NPB][72];    // GEMM result

    const __half2* hw_in = reinterpret_cast<const __half2*>(dir ? g_hwB : g_hwA);
    __half*        hw_out = dir ? g_hwA : g_hwB;

    int t = threadIdx.x;
    int wid = t >> 5;
    int lane = t & 31;
    int nbase = blockIdx.x * NPB;

    // stage W (64x64 -> half): threads 0..127, 32 elements each
    if (t < 128) {
        int rowW = t >> 1;
        int partW = (t & 1) * 32;
        const float4* src = reinterpret_cast<const float4*>(&Wn[rowW * DD + partW]);
        __half2* dst = reinterpret_cast<__half2*>(&Ws[rowW][partW]);
        #pragma unroll
        for (int i = 0; i < 8; i++) {
            float4 v = src[i];
            dst[2 * i]     = __floats2half2_rn(v.x, v.y);
            dst[2 * i + 1] = __floats2half2_rn(v.z, v.w);
        }
    }

    // gather 2 nodes per warp -> Hs
    #pragma unroll
    for (int q = 0; q < 2; q++) {
        int r = wid * 2 + q;
        int n = nbase + r;                      // NN % NPB == 0, always valid
        float2 o = gather_node(hw_in, n, lane, b, lw, lb);
        reinterpret_cast<__half2*>(&Hs[r][0])[lane] = __floats2half2_rn(o.x, o.y);
    }
    __syncthreads();

    // GEMM: 16x64 @ 64x64, warps 0-3 each own one 16-col tile
    if (wid < 4) {
        wmma::fragment<wmma::accumulator, 16, 16, 16, float> acc;
        wmma::fill_fragment(acc, 0.0f);
        #pragma unroll
        for (int k = 0; k < 4; k++) {
            wmma::fragment<wmma::matrix_a, 16, 16, 16, __half, wmma::row_major> af;
            wmma::fragment<wmma::matrix_b, 16, 16, 16, __half, wmma::row_major> bf;
            wmma::load_matrix_sync(af, &Hs[0][k * 16], 72);
            wmma::load_matrix_sync(bf, &Ws[k * 16][wid * 16], 72);
            wmma::mma_sync(acc, af, bf, acc);
        }
        wmma::store_matrix_sync(&Cs[0][wid * 16], acc, 72, wmma::mem_row_major);
    }
    __syncthreads();

    // write 16 rows x 64 cols (half): thread -> row t>>4, cols (t&15)*4
    {
        int r = t >> 4;
        int c = (t & 15) * 4;
        int n = nbase + r;
        __half2* dst = reinterpret_cast<__half2*>(&hw_out[n * DD + c]);
        dst[0] = __floats2half2_rn(Cs[r][c],     Cs[r][c + 1]);
        dst[1] = __floats2half2_rn(Cs[r][c + 2], Cs[r][c + 3]);
    }
}

// ---------------- last layer: gather + LN + ReLU + pool (reads A) ------------
__global__ void k_gather_pool(const float* __restrict__ b,
                              const float* __restrict__ lw,
                              const float* __restrict__ lb,
                              const void* __restrict__ batch) {
    int n = (blockIdx.x * blockDim.x + threadIdx.x) >> 5;
    int lane = threadIdx.x & 31;
    if (n >= NN) return;
    const __half2* hw2 = reinterpret_cast<const __half2*>(g_hwA);
    float2 o = gather_node(hw2, n, lane, b, lw, lb);
    int g = clampi(read_idx(batch, n), NG);
    atomicAdd(&g_pool[g * DD + 2 * lane],     o.x);
    atomicAdd(&g_pool[g * DD + 2 * lane + 1], o.y);
}

// ---------------- output projection ------------------------------------------
__global__ void k_final(const float* __restrict__ Wo, const float* __restrict__ bo,
                        float* __restrict__ out) {
    int g = blockIdx.x;
    int j = threadIdx.x;          // 0..31
    float inv = 1.0f / fmaxf(g_cnt[g], 1.0f);
    float acc = bo[j];
    #pragma unroll
    for (int k = 0; k < DD; k++)
        acc += g_pool[g * DD + k] * inv * Wo[k * DOUT + j];
    out[g * DOUT + j] = acc;
}

// ---------------- launch -----------------------------------------------------
extern "C" void kernel_launch(void* const* d_in, const int* in_sizes, int n_in,
                              void* d_out, int out_size) {
    const float* x      = (const float*)d_in[0];
    const void*  ei     = d_in[1];                 // int32 or int64 (probed)
    const void*  batch  = d_in[2];
    const float* W_in   = (const float*)d_in[3];
    const float* b_in   = (const float*)d_in[4];
    const float* ln_in_w= (const float*)d_in[5];
    const float* ln_in_b= (const float*)d_in[6];
    const float* W_h    = (const float*)d_in[7];   // [2,64,64]
    const float* b_h    = (const float*)d_in[8];   // [2,64]
    const float* ln_h_w = (const float*)d_in[9];   // [2,64]
    const float* ln_h_b = (const float*)d_in[10];  // [2,64]
    const float* W_out  = (const float*)d_in[11];
    const float* b_out  = (const float*)d_in[12];
    float* out = (float*)d_out;

    const int T = 256;
    const int nGrid = (NN + T - 1) / T;
    const int eGrid = (NE + T - 1) / T;

    // CSR + norm build (once per call)
    k_prep  <<<nGrid, T>>>((const int*)ei);
    k_deg   <<<eGrid, T>>>(ei);
    k_alloc <<<nGrid, T>>>(batch);
    k_bucket<<<eGrid, T>>>();

    const int mmGrid = (NN + MM_ROWS - 1) / MM_ROWS;   // 391
    const int fGrid  = NN / NPB;                        // 3125 (exact)
    const int gGrid  = (NN * 32 + T - 1) / T;           // 6250

    k_matmul0    <<<mmGrid, T>>>(x, W_in);                                  // x@W_in -> A
    k_gather_mm  <<<fGrid, T>>>(0, b_in, ln_in_w, ln_in_b, W_h);            // A -> B
    k_gather_mm  <<<fGrid, T>>>(1, b_h, ln_h_w, ln_h_b, W_h + DD * DD);     // B -> A
    k_gather_pool<<<gGrid, T>>>(b_h + DD, ln_h_w + DD, ln_h_b + DD, batch); // A -> pool
    k_final      <<<NG, DOUT>>>(W_out, b_out, out);
}

// round 14
// speedup vs baseline: 1.3648x; 1.3648x over previous
#include <cuda_runtime.h>
#include <cuda_bf16.h>
#include <cuda_fp16.h>
#include <mma.h>
#include <cstdint>

using namespace nvcuda;

#define NN 50000
#define NE 800000
#define NG 512
#define DD 64
#define DOUT 32
#define LN_EPS 1e-5f
#define MM_ROWS 128

// ---------------- scratch (static device globals; 16B aligned) --------------
__device__ int g_is64;                            // 1 if index inputs are int64
__device__ int g_alloc;                           // CSR allocation cursor
__device__ __align__(16) int      g_edeg[NN];     // edge in-degree (no self loop)
__device__ __align__(16) float    g_dinv[NN];
__device__ __align__(16) int      g_src[NE];
__device__ __align__(16) int      g_dst[NE];
__device__ __align__(16) int      g_rowstart[NN]; // CSR row offsets (unordered alloc)
__device__ __align__(16) int      g_cursor[NN];
__device__ __align__(16) uint32_t g_csr[NE];      // CSR: {src:u16 | weight:half << 16}
__device__ __align__(16) __half   g_h[NN * DD];   // layer activations (fp16)
__device__ __align__(16) __half   g_hw[NN * DD];  // h @ W (fp16)
__device__ __align__(16) float    g_pool[NG * DD];
__device__ __align__(16) float    g_cnt[NG];

// ---------------- helpers ---------------------------------------------------
__device__ __forceinline__ float warp_sum(float v) {
    #pragma unroll
    for (int o = 16; o > 0; o >>= 1) v += __shfl_xor_sync(0xffffffffu, v, o);
    return v;
}
__device__ __forceinline__ int clampi(int v, int hi) {   // [0, hi)
    return v < 0 ? 0 : (v >= hi ? hi - 1 : v);
}
__device__ __forceinline__ int read_idx(const void* p, int i) {
    if (g_is64) return (int)((const long long*)p)[i];
    return ((const int*)p)[i];
}

// ---------------- setup kernels ---------------------------------------------
__global__ void k_prep(const int* __restrict__ raw) {
    int i = blockIdx.x * blockDim.x + threadIdx.x;
    if (i < NN) g_edeg[i] = 0;
    if (i < NG) g_cnt[i] = 0.0f;
    if (i == 0) g_alloc = 0;
    if (blockIdx.x == 0) {
        __shared__ int any;
        if (threadIdx.x == 0) any = 0;
        __syncthreads();
        if (raw[2 * threadIdx.x + 1] != 0) atomicOr(&any, 1);
        __syncthreads();
        if (threadIdx.x == 0) g_is64 = (any == 0) ? 1 : 0;
    }
}

__global__ void k_deg(const void* __restrict__ ei) {
    int e = blockIdx.x * blockDim.x + threadIdx.x;
    if (e >= NE) return;
    int s = clampi(read_idx(ei, e), NN);
    int d = clampi(read_idx(ei, NE + e), NN);
    g_src[e] = s;
    g_dst[e] = d;
    atomicAdd(&g_edeg[d], 1);
}

// CSR slot allocation (order-free) + dinv + pool zero + graph-size histogram.
__global__ void k_alloc(const void* __restrict__ batch) {
    int i = blockIdx.x * blockDim.x + threadIdx.x;
    if (i < NG * DD) g_pool[i] = 0.0f;
    if (i >= NN) return;
    int d = g_edeg[i];
    g_dinv[i] = rsqrtf((float)(d + 1));   // +1 self loop
    int r = atomicAdd(&g_alloc, d);
    g_rowstart[i] = r;
    g_cursor[i] = r;
    atomicAdd(&g_cnt[clampi(read_idx(batch, i), NG)], 1.0f);
}

// packed 4B CSR entry: halves the random-scatter sector traffic vs int2.
__global__ void k_bucket() {
    int e = blockIdx.x * blockDim.x + threadIdx.x;
    if (e >= NE) return;
    int s = g_src[e];
    int d = g_dst[e];
    float w = g_dinv[s] * g_dinv[d];
    unsigned short wb = __half_as_ushort(__float2half_rn(w));
    int pos = atomicAdd(&g_cursor[d], 1);
    g_csr[pos] = (uint32_t)s | ((uint32_t)wb << 16);
}

// ---------------- GEMM: g_hw = in @ W via wmma (HMMA fp16 -> fp32 acc) ------
__global__ void k_matmul(int use_h, const float* __restrict__ xin,
                         const float* __restrict__ W) {
    __shared__ __align__(16) char sbuf[128 * 72 * 4];
    __half (*As)[72] = reinterpret_cast<__half (*)[72]>(sbuf);
    __half (*Bs)[72] = reinterpret_cast<__half (*)[72]>(sbuf + 128 * 72 * 2);
    float  (*Cs)[72] = reinterpret_cast<float  (*)[72]>(sbuf);

    int t = threadIdx.x;
    int base = blockIdx.x * MM_ROWS;
    int row = t >> 1;
    int part = (t & 1) * 32;
    int grow = base + row;

    if (grow < NN) {
        if (use_h) {
            const int4* src = reinterpret_cast<const int4*>(&g_h[grow * DD + part]);
            int4* dst = reinterpret_cast<int4*>(&As[row][part]);
            #pragma unroll
            for (int i = 0; i < 4; i++) dst[i] = src[i];
        } else {
            const float4* src = reinterpret_cast<const float4*>(&xin[grow * DD + part]);
            __half2* dst = reinterpret_cast<__half2*>(&As[row][part]);
            #pragma unroll
            for (int i = 0; i < 8; i++) {
                float4 v = src[i];
                dst[2 * i]     = __floats2half2_rn(v.x, v.y);
                dst[2 * i + 1] = __floats2half2_rn(v.z, v.w);
            }
        }
    } else {
        int4 z = make_int4(0, 0, 0, 0);
        int4* dst = reinterpret_cast<int4*>(&As[row][part]);
        #pragma unroll
        for (int i = 0; i < 4; i++) dst[i] = z;
    }
    if (t < 128) {
        int brow = t >> 1;
        int bpart = (t & 1) * 32;
        const float4* src = reinterpret_cast<const float4*>(&W[brow * DD + bpart]);
        __half2* dst = reinterpret_cast<__half2*>(&Bs[brow][bpart]);
        #pragma unroll
        for (int i = 0; i < 8; i++) {
            float4 v = src[i];
            dst[2 * i]     = __floats2half2_rn(v.x, v.y);
            dst[2 * i + 1] = __floats2half2_rn(v.z, v.w);
        }
    }
    __syncthreads();

    int w = t >> 5;
    wmma::fragment<wmma::accumulator, 16, 16, 16, float> acc[4];
    #pragma unroll
    for (int n = 0; n < 4; n++) wmma::fill_fragment(acc[n], 0.0f);
    #pragma unroll
    for (int k = 0; k < 4; k++) {
        wmma::fragment<wmma::matrix_a, 16, 16, 16, __half, wmma::row_major> af;
        wmma::load_matrix_sync(af, &As[w * 16][k * 16], 72);
        #pragma unroll
        for (int n = 0; n < 4; n++) {
            wmma::fragment<wmma::matrix_b, 16, 16, 16, __half, wmma::row_major> bf;
            wmma::load_matrix_sync(bf, &Bs[k * 16][n * 16], 72);
            wmma::mma_sync(acc[n], af, bf, acc[n]);
        }
    }
    __syncthreads();
    #pragma unroll
    for (int n = 0; n < 4; n++)
        wmma::store_matrix_sync(&Cs[w * 16][n * 16], acc[n], 72, wmma::mem_row_major);
    __syncthreads();

    if (grow < NN) {
        __half2* dst = reinterpret_cast<__half2*>(&g_hw[grow * DD + part]);
        #pragma unroll
        for (int i = 0; i < 16; i++)
            dst[i] = __floats2half2_rn(Cs[row][part + 2 * i], Cs[row][part + 2 * i + 1]);
    }
}

// ---------------- fused gather + bias + LN + ReLU (+ pool on last) ----------
// one warp per node; lane handles cols 2*lane, 2*lane+1. No smem, no barriers.
__global__ void k_gather_ln(const float* __restrict__ b,
                            const float* __restrict__ lw,
                            const float* __restrict__ lb,
                            int last, const void* __restrict__ batch) {
    int n = (blockIdx.x * blockDim.x + threadIdx.x) >> 5;
    int lane = threadIdx.x & 31;
    if (n >= NN) return;

    const __half2* hw2 = reinterpret_cast<const __half2*>(g_hw);

    float ws = g_dinv[n]; ws *= ws;
    float2 bb = reinterpret_cast<const float2*>(b)[lane];
    float2 self = __half22float2(hw2[n * 32 + lane]);
    float a0 = bb.x + ws * self.x;
    float a1 = bb.y + ws * self.y;

    int beg = g_rowstart[n];
    int cnt = g_edeg[n];
    #pragma unroll 4
    for (int j = 0; j < cnt; j++) {
        uint32_t p = g_csr[beg + j];
        int s = (int)(p & 0xFFFFu);
        float w = __half2float(__ushort_as_half((unsigned short)(p >> 16)));
        float2 v = __half22float2(hw2[s * 32 + lane]);
        a0 += w * v.x;
        a1 += w * v.y;
    }

    float mu = warp_sum(a0 + a1) * (1.0f / DD);
    float d0 = a0 - mu, d1 = a1 - mu;
    float var = warp_sum(d0 * d0 + d1 * d1) * (1.0f / DD);
    float rs = rsqrtf(var + LN_EPS);
    float2 w2 = reinterpret_cast<const float2*>(lw)[lane];
    float2 lb2 = reinterpret_cast<const float2*>(lb)[lane];
    float o0 = fmaxf(d0 * rs * w2.x + lb2.x, 0.0f);
    float o1 = fmaxf(d1 * rs * w2.y + lb2.y, 0.0f);
    reinterpret_cast<__half2*>(g_h)[n * 32 + lane] = __floats2half2_rn(o0, o1);

    if (last) {
        int g = clampi(read_idx(batch, n), NG);
        atomicAdd(&g_pool[g * DD + 2 * lane],     o0);
        atomicAdd(&g_pool[g * DD + 2 * lane + 1], o1);
    }
}

// ---------------- output projection ------------------------------------------
__global__ void k_final(const float* __restrict__ Wo, const float* __restrict__ bo,
                        float* __restrict__ out) {
    int g = blockIdx.x;
    int j = threadIdx.x;          // 0..31
    float inv = 1.0f / fmaxf(g_cnt[g], 1.0f);
    float acc = bo[j];
    #pragma unroll
    for (int k = 0; k < DD; k++)
        acc += g_pool[g * DD + k] * inv * Wo[k * DOUT + j];
    out[g * DOUT + j] = acc;
}

// ---------------- launch -----------------------------------------------------
extern "C" void kernel_launch(void* const* d_in, const int* in_sizes, int n_in,
                              void* d_out, int out_size) {
    const float* x      = (const float*)d_in[0];
    const void*  ei     = d_in[1];                 // int32 or int64 (probed)
    const void*  batch  = d_in[2];
    const float* W_in   = (const float*)d_in[3];
    const float* b_in   = (const float*)d_in[4];
    const float* ln_in_w= (const float*)d_in[5];
    const float* ln_in_b= (const float*)d_in[6];
    const float* W_h    = (const float*)d_in[7];   // [2,64,64]
    const float* b_h    = (const float*)d_in[8];   // [2,64]
    const float* ln_h_w = (const float*)d_in[9];   // [2,64]
    const float* ln_h_b = (const float*)d_in[10];  // [2,64]
    const float* W_out  = (const float*)d_in[11];
    const float* b_out  = (const float*)d_in[12];
    float* out = (float*)d_out;

    const int T = 256;
    const int nGrid = (NN + T - 1) / T;
    const int eGrid = (NE + T - 1) / T;

    // CSR + norm build (once per call)
    k_prep  <<<nGrid, T>>>((const int*)ei);
    k_deg   <<<eGrid, T>>>(ei);
    k_alloc <<<nGrid, T>>>(batch);
    k_bucket<<<eGrid, T>>>();

    const int mmGrid = (NN + MM_ROWS - 1) / MM_ROWS;   // 391
    const int gGrid  = (NN * 32 + T - 1) / T;          // 1 warp/node

    // layer 0
    k_matmul   <<<mmGrid, T>>>(0, x, W_in);
    k_gather_ln<<<gGrid, T>>>(b_in, ln_in_w, ln_in_b, 0, batch);
    // hidden layers (second one is the last -> fold pooling)
    for (int i = 0; i < 2; i++) {
        k_matmul   <<<mmGrid, T>>>(1, nullptr, W_h + i * DD * DD);
        k_gather_ln<<<gGrid, T>>>(b_h + i * DD, ln_h_w + i * DD, ln_h_b + i * DD,
                                  i == 1, batch);
    }
    k_final<<<NG, DOUT>>>(W_out, b_out, out);
}